// round 4
// baseline (speedup 1.0000x reference)
#include <cuda_runtime.h>

#define NN 100000
#define EE 3200000

// ---------------- scratch (device globals: no allocs allowed) ----------------
__device__ int   g_src[EE];
__device__ int   g_dst[EE];
__device__ int   g_col[EE];
__device__ float g_w[EE];
__device__ int   g_indeg[NN];
__device__ float g_dinv[NN];
__device__ int   g_rowptr[NN];
__device__ int   g_cursor[NN];
__device__ int   g_ctr;
__device__ float g_zagg[NN * 16];
__device__ float g_h1[NN * 256];
__device__ float g_hagg[NN * 256];
__device__ float g_h2[NN * 256];

// ---------------- 1) init ----------------
__global__ void k_zero() {
    int i = blockIdx.x * blockDim.x + threadIdx.x;
    if (i < NN) g_indeg[i] = 0;
    if (i == 0) g_ctr = 0;
}

// ---------------- 2) histogram in-degree + edge copy (edge_index is int32!) --
__global__ void k_hist(const int* __restrict__ ei) {
    int e = blockIdx.x * blockDim.x + threadIdx.x;
    if (e >= EE) return;
    int s = ei[e];
    int d = ei[EE + e];
    g_src[e] = s;
    g_dst[e] = d;
    atomicAdd(&g_indeg[d], 1);
}

// ---------------- 3) dinv = 1/sqrt(indeg + 1)  (self-loop included) ----------
__global__ void k_dinv() {
    int i = blockIdx.x * blockDim.x + threadIdx.x;
    if (i < NN) g_dinv[i] = rsqrtf((float)g_indeg[i] + 1.0f);
}

// ---------------- 4) rowptr: block-local scan + atomic block base ------------
__global__ void k_rowptr() {
    __shared__ int ssum[512];
    __shared__ int sbase;
    int i = blockIdx.x * 512 + threadIdx.x;
    int v = (i < NN) ? g_indeg[i] : 0;
    ssum[threadIdx.x] = v;
    __syncthreads();
    // Hillis-Steele inclusive scan
    for (int off = 1; off < 512; off <<= 1) {
        int x = (threadIdx.x >= off) ? ssum[threadIdx.x - off] : 0;
        __syncthreads();
        ssum[threadIdx.x] += x;
        __syncthreads();
    }
    if (threadIdx.x == 511) sbase = atomicAdd(&g_ctr, ssum[511]);
    __syncthreads();
    if (i < NN) {
        int start = sbase + ssum[threadIdx.x] - v;  // exclusive
        g_rowptr[i] = start;
        g_cursor[i] = start;
    }
}

// ---------------- 5) scatter edges into CSR (by dst), fold in edge weight ----
__global__ void k_scatter() {
    int e = blockIdx.x * blockDim.x + threadIdx.x;
    if (e >= EE) return;
    int d = g_dst[e];
    int s = g_src[e];
    int p = atomicAdd(&g_cursor[d], 1);
    g_col[p] = s;
    g_w[p] = g_dinv[s] * g_dinv[d];
}

// ---------------- 6) 16-dim aggregation of z (agg commutes with @W1) ---------
// warp per node; lanes split into 2 half-warps x 16 features
__global__ void k_agg16(const float* __restrict__ z) {
    int t = blockIdx.x * blockDim.x + threadIdx.x;
    int n = t >> 5;
    if (n >= NN) return;
    int lane = t & 31;
    int half = lane >> 4;
    int k = lane & 15;
    int st = g_rowptr[n], cnt = g_indeg[n];
    float acc = 0.0f;
    for (int j = half; j < cnt; j += 2) {
        int s = __ldg(&g_col[st + j]);
        float wv = __ldg(&g_w[st + j]);
        acc += wv * __ldg(&z[s * 16 + k]);
    }
    acc += __shfl_xor_sync(0xffffffffu, acc, 16);
    if (half == 0) {
        float di = g_dinv[n];
        g_zagg[n * 16 + k] = acc + di * di * __ldg(&z[n * 16 + k]);
    }
}

// ---------------- 7) GEMM1: h1 = zagg @ W1 + b1  (100k x 16 x 256) -----------
__global__ void k_gemm1(const float* __restrict__ W1, const float* __restrict__ b1) {
    __shared__ float sW[16 * 256];
    __shared__ float sb[256];
    __shared__ float sz[64 * 16];
    int t = threadIdx.x;
    #pragma unroll
    for (int k = 0; k < 16; k++) sW[k * 256 + t] = W1[k * 256 + t];
    sb[t] = b1[t];
    int nb = blockIdx.x * 64;
    for (int i = t; i < 64 * 16; i += 256) {
        int n = nb + (i >> 4);
        sz[i] = (n < NN) ? g_zagg[nb * 16 + i] : 0.0f;
    }
    __syncthreads();
    for (int m = 0; m < 64; m++) {
        int n = nb + m;
        if (n >= NN) break;
        float acc = sb[t];
        #pragma unroll
        for (int k = 0; k < 16; k++) acc += sz[m * 16 + k] * sW[k * 256 + t];
        g_h1[n * 256 + t] = acc;
    }
}

// ---------------- 8) 256-dim aggregation of h1 (agg commutes with @W2) -------
// warp per node; each lane holds 8 features as 2 float4s
__global__ void k_agg256() {
    int t = blockIdx.x * blockDim.x + threadIdx.x;
    int n = t >> 5;
    if (n >= NN) return;
    int lane = t & 31;
    int st = g_rowptr[n], cnt = g_indeg[n];
    const float4* H = reinterpret_cast<const float4*>(g_h1);
    float4 a0 = make_float4(0.f, 0.f, 0.f, 0.f);
    float4 a1 = make_float4(0.f, 0.f, 0.f, 0.f);
    #pragma unroll 2
    for (int j = 0; j < cnt; j++) {
        int s = __ldg(&g_col[st + j]);
        float wv = __ldg(&g_w[st + j]);
        float4 v0 = H[s * 64 + lane];
        float4 v1 = H[s * 64 + 32 + lane];
        a0.x += wv * v0.x; a0.y += wv * v0.y; a0.z += wv * v0.z; a0.w += wv * v0.w;
        a1.x += wv * v1.x; a1.y += wv * v1.y; a1.z += wv * v1.z; a1.w += wv * v1.w;
    }
    float di = g_dinv[n];
    float c = di * di;
    float4 v0 = H[n * 64 + lane];
    float4 v1 = H[n * 64 + 32 + lane];
    a0.x += c * v0.x; a0.y += c * v0.y; a0.z += c * v0.z; a0.w += c * v0.w;
    a1.x += c * v1.x; a1.y += c * v1.y; a1.z += c * v1.z; a1.w += c * v1.w;
    float4* G = reinterpret_cast<float4*>(g_hagg);
    G[n * 64 + lane] = a0;
    G[n * 64 + 32 + lane] = a1;
}

// ---------------- 9) GEMM2: h2 = hagg @ W2 + b2  (100k x 256 x 256) ----------
// block: 32 nodes x 256 cols; thread: 8 nodes x 4 cols register tile
__global__ void k_gemm2(const float* __restrict__ W2, const float* __restrict__ b2) {
    __shared__ __align__(16) float sW[32 * 256];   // sW[kk][c]
    __shared__ __align__(16) float sH[32 * 36];    // sH[kk][m], padded stride 36
    int t = threadIdx.x;
    int tc = t & 63;    // col group: cols 4*tc .. 4*tc+3
    int tm = t >> 6;    // node group: nodes 8*tm .. 8*tm+7
    int nb = blockIdx.x * 32;

    float4 acc[8];
    #pragma unroll
    for (int i = 0; i < 8; i++) acc[i] = make_float4(0.f, 0.f, 0.f, 0.f);

    const float4* W2v = reinterpret_cast<const float4*>(W2);
    float4* sWv = reinterpret_cast<float4*>(sW);

    for (int kt = 0; kt < 8; kt++) {
        // fill W2 k-tile: rows [32kt, 32kt+32) x 256 cols = 2048 float4s
        #pragma unroll
        for (int i = 0; i < 8; i++) sWv[t + i * 256] = W2v[kt * 2048 + t + i * 256];
        // fill transposed h tile
        {
            int m = t >> 3;
            int kk4 = (t & 7) * 4;
            int n = nb + m;
            float4 v = make_float4(0.f, 0.f, 0.f, 0.f);
            if (n < NN) v = *reinterpret_cast<const float4*>(&g_hagg[n * 256 + kt * 32 + kk4]);
            sH[(kk4 + 0) * 36 + m] = v.x;
            sH[(kk4 + 1) * 36 + m] = v.y;
            sH[(kk4 + 2) * 36 + m] = v.z;
            sH[(kk4 + 3) * 36 + m] = v.w;
        }
        __syncthreads();
        #pragma unroll 8
        for (int kk = 0; kk < 32; kk++) {
            float4 wv = *reinterpret_cast<const float4*>(&sW[kk * 256 + tc * 4]);
            float4 h0 = *reinterpret_cast<const float4*>(&sH[kk * 36 + tm * 8]);
            float4 h1 = *reinterpret_cast<const float4*>(&sH[kk * 36 + tm * 8 + 4]);
            acc[0].x += h0.x * wv.x; acc[0].y += h0.x * wv.y; acc[0].z += h0.x * wv.z; acc[0].w += h0.x * wv.w;
            acc[1].x += h0.y * wv.x; acc[1].y += h0.y * wv.y; acc[1].z += h0.y * wv.z; acc[1].w += h0.y * wv.w;
            acc[2].x += h0.z * wv.x; acc[2].y += h0.z * wv.y; acc[2].z += h0.z * wv.z; acc[2].w += h0.z * wv.w;
            acc[3].x += h0.w * wv.x; acc[3].y += h0.w * wv.y; acc[3].z += h0.w * wv.z; acc[3].w += h0.w * wv.w;
            acc[4].x += h1.x * wv.x; acc[4].y += h1.x * wv.y; acc[4].z += h1.x * wv.z; acc[4].w += h1.x * wv.w;
            acc[5].x += h1.y * wv.x; acc[5].y += h1.y * wv.y; acc[5].z += h1.y * wv.z; acc[5].w += h1.y * wv.w;
            acc[6].x += h1.z * wv.x; acc[6].y += h1.z * wv.y; acc[6].z += h1.z * wv.z; acc[6].w += h1.z * wv.w;
            acc[7].x += h1.w * wv.x; acc[7].y += h1.w * wv.y; acc[7].z += h1.w * wv.z; acc[7].w += h1.w * wv.w;
        }
        __syncthreads();
    }

    float4 bias = *reinterpret_cast<const float4*>(&b2[tc * 4]);
    #pragma unroll
    for (int i = 0; i < 8; i++) {
        int n = nb + tm * 8 + i;
        if (n < NN) {
            float4 r;
            r.x = acc[i].x + bias.x;
            r.y = acc[i].y + bias.y;
            r.z = acc[i].z + bias.z;
            r.w = acc[i].w + bias.w;
            *reinterpret_cast<float4*>(&g_h2[n * 256 + tc * 4]) = r;
        }
    }
}

// ---------------- 10) edge dot + sigmoid  (warp per edge) --------------------
__global__ void k_edge(float* __restrict__ out) {
    int t = blockIdx.x * blockDim.x + threadIdx.x;
    int e = t >> 5;
    if (e >= EE) return;
    int lane = t & 31;
    int s = g_src[e];
    int d = g_dst[e];
    const float4* H = reinterpret_cast<const float4*>(g_h2);
    float4 a0 = H[s * 64 + lane];
    float4 b0 = H[d * 64 + lane];
    float4 a1 = H[s * 64 + 32 + lane];
    float4 b1 = H[d * 64 + 32 + lane];
    float sum = a0.x * b0.x + a0.y * b0.y + a0.z * b0.z + a0.w * b0.w
              + a1.x * b1.x + a1.y * b1.y + a1.z * b1.z + a1.w * b1.w;
    #pragma unroll
    for (int o = 16; o > 0; o >>= 1) sum += __shfl_xor_sync(0xffffffffu, sum, o);
    if (lane == 0) out[e] = 1.0f / (1.0f + __expf(-sum));
}

// ---------------- launch ------------------------------------------------------
extern "C" void kernel_launch(void* const* d_in, const int* in_sizes, int n_in,
                              void* d_out, int out_size) {
    const float* z  = (const float*)d_in[0];
    const int*   ei = (const int*)d_in[1];      // edge_index: int32 (JAX x64 disabled)
    const float* W1 = (const float*)d_in[2];
    const float* b1 = (const float*)d_in[3];
    const float* W2 = (const float*)d_in[4];
    const float* b2 = (const float*)d_in[5];
    float* out = (float*)d_out;

    k_zero<<<(NN + 255) / 256, 256>>>();
    k_hist<<<(EE + 255) / 256, 256>>>(ei);
    k_dinv<<<(NN + 255) / 256, 256>>>();
    k_rowptr<<<(NN + 511) / 512, 512>>>();
    k_scatter<<<(EE + 255) / 256, 256>>>();
    k_agg16<<<(NN * 32 + 255) / 256, 256>>>(z);
    k_gemm1<<<(NN + 63) / 64, 256>>>(W1, b1);
    k_agg256<<<(NN * 32 + 255) / 256, 256>>>();
    k_gemm2<<<(NN + 31) / 32, 256>>>(W2, b2);
    k_edge<<<((long long)EE * 32 + 255) / 256, 256>>>(out);
}

// round 7
// speedup vs baseline: 4.5596x; 4.5596x over previous
#include <cuda_runtime.h>

#define NN 100000
#define EE 3200000

// ---------------- scratch (device globals: no allocs allowed) ----------------
__device__ int   g_src[EE];
__device__ int   g_dst[EE];
__device__ int   g_col[EE];
__device__ float g_ew[EE];
__device__ int   g_indeg[NN];
__device__ float g_dinv[NN];
__device__ int   g_rowptr[NN];
__device__ int   g_cursor[NN];
__device__ int   g_ctr;
__device__ float g_zagg1[NN * 16];   // A z
__device__ float g_u[NN * 16];       // A^2 z
__device__ float g_r[NN];            // A 1  (row sums)
__device__ float g_wn[NN * 16];      // per-node: M u + r v1 + v2
__device__ float g_delta[NN];
__device__ float g_eps[NN];
// params
__device__ float g_P[16 * 256];      // W1 @ W2
__device__ float g_q[256];           // b1 @ W2
__device__ float g_M[16 * 16];       // P P^T
__device__ float g_v1[16];           // P q^T
__device__ float g_v2[16];           // P b2^T
__device__ float g_sc[3];            // qq, qb, bb

// ---------------- 1) init ----------------
__global__ void k_zero() {
    int i = blockIdx.x * blockDim.x + threadIdx.x;
    if (i < NN) g_indeg[i] = 0;
    if (i == 0) g_ctr = 0;
}

// ---------------- 2) histogram in-degree + edge copy (edge_index is int32) ---
__global__ void k_hist(const int* __restrict__ ei) {
    int e = blockIdx.x * blockDim.x + threadIdx.x;
    if (e >= EE) return;
    int s = ei[e];
    int d = ei[EE + e];
    g_src[e] = s;
    g_dst[e] = d;
    atomicAdd(&g_indeg[d], 1);
}

// ---------------- 3) dinv = 1/sqrt(indeg + 1)  (self-loop included) ----------
__global__ void k_dinv() {
    int i = blockIdx.x * blockDim.x + threadIdx.x;
    if (i < NN) g_dinv[i] = rsqrtf((float)g_indeg[i] + 1.0f);
}

// ---------------- 4) rowptr: block-local scan + atomic block base ------------
__global__ void k_rowptr() {
    __shared__ int ssum[512];
    __shared__ int sbase;
    int i = blockIdx.x * 512 + threadIdx.x;
    int v = (i < NN) ? g_indeg[i] : 0;
    ssum[threadIdx.x] = v;
    __syncthreads();
    for (int off = 1; off < 512; off <<= 1) {
        int x = (threadIdx.x >= off) ? ssum[threadIdx.x - off] : 0;
        __syncthreads();
        ssum[threadIdx.x] += x;
        __syncthreads();
    }
    if (threadIdx.x == 511) sbase = atomicAdd(&g_ctr, ssum[511]);
    __syncthreads();
    if (i < NN) {
        int start = sbase + ssum[threadIdx.x] - v;  // exclusive
        g_rowptr[i] = start;
        g_cursor[i] = start;
    }
}

// ---------------- 5) scatter edges into CSR (by dst), fold in edge weight ----
__global__ void k_scatter() {
    int e = blockIdx.x * blockDim.x + threadIdx.x;
    if (e >= EE) return;
    int d = g_dst[e];
    int s = g_src[e];
    int p = atomicAdd(&g_cursor[d], 1);
    g_col[p] = s;
    g_ew[p] = g_dinv[s] * g_dinv[d];
}

// ---------------- 6a) 16-dim aggregation pass 1: zagg1 = A z, r = A 1 --------
// warp per node; lanes split into 2 half-warps x 16 features
__global__ void k_agg16_p1(const float* __restrict__ z) {
    int t = blockIdx.x * blockDim.x + threadIdx.x;
    int n = t >> 5;
    if (n >= NN) return;
    int lane = t & 31;
    int half = lane >> 4;
    int k = lane & 15;
    int st = g_rowptr[n], cnt = g_indeg[n];
    float acc = 0.0f, ws = 0.0f;
    for (int j = half; j < cnt; j += 2) {
        int s = __ldg(&g_col[st + j]);
        float wv = __ldg(&g_ew[st + j]);
        ws += wv;
        acc += wv * __ldg(&z[s * 16 + k]);
    }
    acc += __shfl_xor_sync(0xffffffffu, acc, 16);
    ws  += __shfl_xor_sync(0xffffffffu, ws, 16);
    if (half == 0) {
        float di = g_dinv[n];
        float c = di * di;
        g_zagg1[n * 16 + k] = acc + c * __ldg(&z[n * 16 + k]);
        if (k == 0) g_r[n] = ws + c;
    }
}

// ---------------- 6b) 16-dim aggregation pass 2: u = A zagg1 -----------------
__global__ void k_agg16_p2() {
    int t = blockIdx.x * blockDim.x + threadIdx.x;
    int n = t >> 5;
    if (n >= NN) return;
    int lane = t & 31;
    int half = lane >> 4;
    int k = lane & 15;
    int st = g_rowptr[n], cnt = g_indeg[n];
    float acc = 0.0f;
    for (int j = half; j < cnt; j += 2) {
        int s = __ldg(&g_col[st + j]);
        float wv = __ldg(&g_ew[st + j]);
        acc += wv * __ldg(&g_zagg1[s * 16 + k]);
    }
    acc += __shfl_xor_sync(0xffffffffu, acc, 16);
    if (half == 0) {
        float di = g_dinv[n];
        g_u[n * 16 + k] = acc + di * di * g_zagg1[n * 16 + k];
    }
}

// ---------------- 7a) params A: P = W1@W2 (16x256), q = b1@W2 (256) ----------
__global__ void k_paramsA(const float* __restrict__ W1, const float* __restrict__ b1,
                          const float* __restrict__ W2) {
    __shared__ float sW1[16 * 256];
    __shared__ float sb1[256];
    int t = threadIdx.x;  // 256
    #pragma unroll
    for (int i = 0; i < 16; i++) sW1[i * 256 + t] = W1[i * 256 + t];
    sb1[t] = b1[t];
    __syncthreads();
    float p[16];
    #pragma unroll
    for (int i = 0; i < 16; i++) p[i] = 0.0f;
    float qa = 0.0f;
    for (int k = 0; k < 256; k++) {
        float wv = W2[k * 256 + t];
        qa += sb1[k] * wv;
        #pragma unroll
        for (int i = 0; i < 16; i++) p[i] += sW1[i * 256 + k] * wv;
    }
    #pragma unroll
    for (int i = 0; i < 16; i++) g_P[i * 256 + t] = p[i];
    g_q[t] = qa;
}

// ---------------- 7b) params B: M = P P^T, v1 = P q, v2 = P b2, scalars ------
__global__ void k_paramsB(const float* __restrict__ b2) {
    int t = threadIdx.x;  // 256
    int i = t >> 4, j = t & 15;
    float m = 0.0f;
    for (int c = 0; c < 256; c++) m += g_P[i * 256 + c] * g_P[j * 256 + c];
    g_M[i * 16 + j] = m;
    if (t < 16) {
        float a = 0.0f, b = 0.0f;
        for (int c = 0; c < 256; c++) {
            float pv = g_P[t * 256 + c];
            a += pv * g_q[c];
            b += pv * b2[c];
        }
        g_v1[t] = a;
        g_v2[t] = b;
    }
    if (t == 0) {
        float qq = 0.0f, qb = 0.0f, bb = 0.0f;
        for (int c = 0; c < 256; c++) {
            float qc = g_q[c], bc = b2[c];
            qq += qc * qc;
            qb += qc * bc;
            bb += bc * bc;
        }
        g_sc[0] = qq; g_sc[1] = qb; g_sc[2] = bb;
    }
}

// ---------------- 8) per-node records: wn = M u + r v1 + v2, delta, eps ------
__global__ void k_nodes() {
    __shared__ float sM[256], sv1[16], sv2[16], ssc[3];
    int t = threadIdx.x;  // 256
    sM[t] = g_M[t];
    if (t < 16) { sv1[t] = g_v1[t]; sv2[t] = g_v2[t]; }
    if (t < 3) ssc[t] = g_sc[t];
    __syncthreads();
    int n = blockIdx.x * 256 + t;
    if (n >= NN) return;
    float u[16];
    const float4* U4 = reinterpret_cast<const float4*>(g_u);
    #pragma unroll
    for (int i = 0; i < 4; i++) {
        float4 v = U4[n * 4 + i];
        u[i * 4 + 0] = v.x; u[i * 4 + 1] = v.y; u[i * 4 + 2] = v.z; u[i * 4 + 3] = v.w;
    }
    float r = g_r[n];
    float gamma = 0.0f, uv2 = 0.0f;
    float wn[16];
    #pragma unroll
    for (int i = 0; i < 16; i++) {
        float a = 0.0f;
        #pragma unroll
        for (int j = 0; j < 16; j++) a += sM[i * 16 + j] * u[j];
        wn[i] = a + r * sv1[i] + sv2[i];
        gamma += u[i] * sv1[i];
        uv2   += u[i] * sv2[i];
    }
    float4* W4 = reinterpret_cast<float4*>(g_wn);
    #pragma unroll
    for (int i = 0; i < 4; i++)
        W4[n * 4 + i] = make_float4(wn[i * 4], wn[i * 4 + 1], wn[i * 4 + 2], wn[i * 4 + 3]);
    g_delta[n] = gamma + r * ssc[0] + ssc[1];
    g_eps[n]   = uv2 + r * ssc[1] + ssc[2];
}

// ---------------- 9) edge kernel: val = u_s . wn_d + r_s*delta_d + eps_d -----
__global__ void k_edge(float* __restrict__ out) {
    int e = blockIdx.x * blockDim.x + threadIdx.x;
    if (e >= EE) return;
    int s = g_src[e];
    int d = g_dst[e];
    const float4* U = reinterpret_cast<const float4*>(g_u);
    const float4* W = reinterpret_cast<const float4*>(g_wn);
    float dot = 0.0f;
    #pragma unroll
    for (int i = 0; i < 4; i++) {
        float4 a = U[s * 4 + i];
        float4 b = W[d * 4 + i];
        dot += a.x * b.x + a.y * b.y + a.z * b.z + a.w * b.w;
    }
    float val = dot + g_r[s] * g_delta[d] + g_eps[d];
    out[e] = 1.0f / (1.0f + __expf(-val));
}

// ---------------- launch ------------------------------------------------------
extern "C" void kernel_launch(void* const* d_in, const int* in_sizes, int n_in,
                              void* d_out, int out_size) {
    const float* z  = (const float*)d_in[0];
    const int*   ei = (const int*)d_in[1];      // edge_index: int32 (JAX x64 off)
    const float* W1 = (const float*)d_in[2];
    const float* b1 = (const float*)d_in[3];
    const float* W2 = (const float*)d_in[4];
    const float* b2 = (const float*)d_in[5];
    float* out = (float*)d_out;

    k_zero<<<(NN + 255) / 256, 256>>>();
    k_hist<<<(EE + 255) / 256, 256>>>(ei);
    k_dinv<<<(NN + 255) / 256, 256>>>();
    k_rowptr<<<(NN + 511) / 512, 512>>>();
    k_scatter<<<(EE + 255) / 256, 256>>>();
    k_paramsA<<<1, 256>>>(W1, b1, W2);
    k_paramsB<<<1, 256>>>(b2);
    k_agg16_p1<<<(NN * 32 + 255) / 256, 256>>>(z);
    k_agg16_p2<<<(NN * 32 + 255) / 256, 256>>>();
    k_nodes<<<(NN + 255) / 256, 256>>>();
    k_edge<<<(EE + 255) / 256, 256>>>(out);
}

// round 9
// speedup vs baseline: 5.1322x; 1.1256x over previous
#include <cuda_runtime.h>

#define NN 100000
#define EE 3200000

// ---------------- scratch (device globals: no allocs allowed) ----------------
__device__ int   g_col[EE];
__device__ int   g_indeg[NN];
__device__ float g_dinv[NN];
__device__ int   g_rowptr[NN];
__device__ int   g_cursor[NN];
__device__ int   g_ctr;
__device__ float g_t0[NN * 16];      // dinv .* z
__device__ float g_t1[NN * 16];      // dinv .* (A z)
__device__ float g_u[NN * 16];       // A^2 z
__device__ float g_r[NN];            // A 1  (row sums)
__device__ float g_wn[NN * 16];      // per-node: M u + r v1 + v2
__device__ float g_delta[NN];
__device__ float g_eps[NN];
// params
__device__ float g_P[16 * 256];      // W1 @ W2
__device__ float g_q[256];           // b1 @ W2
__device__ float g_M[16 * 16];       // P P^T
__device__ float g_v1[16];           // P q^T
__device__ float g_v2[16];           // P b2^T
__device__ float g_sc[3];            // qq, qb, bb

// ---------------- 1) init ----------------
__global__ void k_zero() {
    int i = blockIdx.x * blockDim.x + threadIdx.x;
    if (i < NN) g_indeg[i] = 0;
    if (i == 0) g_ctr = 0;
}

// ---------------- 2) histogram in-degree (reads dst half of edge_index only) -
__global__ void k_hist(const int* __restrict__ ei) {
    int e = blockIdx.x * blockDim.x + threadIdx.x;
    if (e >= EE) return;
    atomicAdd(&g_indeg[ei[EE + e]], 1);
}

// ---------------- 3) dinv + t0 = dinv .* z  (fused, NN*16 threads) -----------
__global__ void k_dinv_t0(const float* __restrict__ z) {
    int i = blockIdx.x * blockDim.x + threadIdx.x;
    if (i >= NN * 16) return;
    int n = i >> 4;
    float di = rsqrtf((float)g_indeg[n] + 1.0f);
    g_t0[i] = di * z[i];
    if ((i & 15) == 0) g_dinv[n] = di;
}

// ---------------- 4) rowptr: block-local scan + atomic block base ------------
__global__ void k_rowptr() {
    __shared__ int ssum[512];
    __shared__ int sbase;
    int i = blockIdx.x * 512 + threadIdx.x;
    int v = (i < NN) ? g_indeg[i] : 0;
    ssum[threadIdx.x] = v;
    __syncthreads();
    for (int off = 1; off < 512; off <<= 1) {
        int x = (threadIdx.x >= off) ? ssum[threadIdx.x - off] : 0;
        __syncthreads();
        ssum[threadIdx.x] += x;
        __syncthreads();
    }
    if (threadIdx.x == 511) sbase = atomicAdd(&g_ctr, ssum[511]);
    __syncthreads();
    if (i < NN) {
        int start = sbase + ssum[threadIdx.x] - v;  // exclusive
        g_rowptr[i] = start;
        g_cursor[i] = start;
    }
}

// ---------------- 5) scatter edges into CSR (by dst): col only, no weights ---
__global__ void k_scatter(const int* __restrict__ ei) {
    int e = blockIdx.x * blockDim.x + threadIdx.x;
    if (e >= EE) return;
    int s = ei[e];
    int d = ei[EE + e];
    int p = atomicAdd(&g_cursor[d], 1);
    g_col[p] = s;
}

// ---------------- 6a) pass 1: t1 = dinv .* (A z), r = A 1 --------------------
// warp per node; lanes split into 2 half-warps x 16 features
__global__ void k_agg_p1() {
    int t = blockIdx.x * blockDim.x + threadIdx.x;
    int n = t >> 5;
    if (n >= NN) return;
    int lane = t & 31;
    int half = lane >> 4;
    int k = lane & 15;
    int st = g_rowptr[n], cnt = g_indeg[n];
    float acc = 0.0f, ws = 0.0f;
    for (int j = half; j < cnt; j += 2) {
        int s = __ldg(&g_col[st + j]);
        acc += __ldg(&g_t0[s * 16 + k]);
        if (k == 0) ws += __ldg(&g_dinv[s]);
    }
    acc += __shfl_xor_sync(0xffffffffu, acc, 16);
    ws  += __shfl_xor_sync(0xffffffffu, ws, 16);
    if (half == 0) {
        float di = g_dinv[n];
        g_t1[n * 16 + k] = di * di * (acc + __ldg(&g_t0[n * 16 + k]));
        if (k == 0) g_r[n] = di * (ws + di);
    }
}

// ---------------- 6b) pass 2: u = A (A z) = dinv .* (sum t1 + t1_self) -------
__global__ void k_agg_p2() {
    int t = blockIdx.x * blockDim.x + threadIdx.x;
    int n = t >> 5;
    if (n >= NN) return;
    int lane = t & 31;
    int half = lane >> 4;
    int k = lane & 15;
    int st = g_rowptr[n], cnt = g_indeg[n];
    float acc = 0.0f;
    for (int j = half; j < cnt; j += 2) {
        int s = __ldg(&g_col[st + j]);
        acc += __ldg(&g_t1[s * 16 + k]);
    }
    acc += __shfl_xor_sync(0xffffffffu, acc, 16);
    if (half == 0) {
        float di = g_dinv[n];
        g_u[n * 16 + k] = di * (acc + g_t1[n * 16 + k]);
    }
}

// ---------------- 7a) params A: P = W1@W2 (16x256), q = b1@W2 (256) ----------
__global__ void k_paramsA(const float* __restrict__ W1, const float* __restrict__ b1,
                          const float* __restrict__ W2) {
    __shared__ float sW1[16 * 256];
    __shared__ float sb1[256];
    int t = threadIdx.x;  // 256
    #pragma unroll
    for (int i = 0; i < 16; i++) sW1[i * 256 + t] = W1[i * 256 + t];
    sb1[t] = b1[t];
    __syncthreads();
    float p[16];
    #pragma unroll
    for (int i = 0; i < 16; i++) p[i] = 0.0f;
    float qa = 0.0f;
    for (int k = 0; k < 256; k++) {
        float wv = W2[k * 256 + t];
        qa += sb1[k] * wv;
        #pragma unroll
        for (int i = 0; i < 16; i++) p[i] += sW1[i * 256 + k] * wv;
    }
    #pragma unroll
    for (int i = 0; i < 16; i++) g_P[i * 256 + t] = p[i];
    g_q[t] = qa;
}

// ---------------- 7b) params B: M = P P^T, v1 = P q, v2 = P b2, scalars ------
__global__ void k_paramsB(const float* __restrict__ b2) {
    int t = threadIdx.x;  // 256
    int i = t >> 4, j = t & 15;
    float m = 0.0f;
    for (int c = 0; c < 256; c++) m += g_P[i * 256 + c] * g_P[j * 256 + c];
    g_M[i * 16 + j] = m;
    if (t < 16) {
        float a = 0.0f, b = 0.0f;
        for (int c = 0; c < 256; c++) {
            float pv = g_P[t * 256 + c];
            a += pv * g_q[c];
            b += pv * b2[c];
        }
        g_v1[t] = a;
        g_v2[t] = b;
    }
    if (t == 0) {
        float qq = 0.0f, qb = 0.0f, bb = 0.0f;
        for (int c = 0; c < 256; c++) {
            float qc = g_q[c], bc = b2[c];
            qq += qc * qc;
            qb += qc * bc;
            bb += bc * bc;
        }
        g_sc[0] = qq; g_sc[1] = qb; g_sc[2] = bb;
    }
}

// ---------------- 8) per-node records: wn = M u + r v1 + v2, delta, eps ------
__global__ void k_nodes() {
    __shared__ float sM[256], sv1[16], sv2[16], ssc[3];
    int t = threadIdx.x;  // 256
    sM[t] = g_M[t];
    if (t < 16) { sv1[t] = g_v1[t]; sv2[t] = g_v2[t]; }
    if (t < 3) ssc[t] = g_sc[t];
    __syncthreads();
    int n = blockIdx.x * 256 + t;
    if (n >= NN) return;
    float u[16];
    const float4* U4 = reinterpret_cast<const float4*>(g_u);
    #pragma unroll
    for (int i = 0; i < 4; i++) {
        float4 v = U4[n * 4 + i];
        u[i * 4 + 0] = v.x; u[i * 4 + 1] = v.y; u[i * 4 + 2] = v.z; u[i * 4 + 3] = v.w;
    }
    float r = g_r[n];
    float gamma = 0.0f, uv2 = 0.0f;
    float wn[16];
    #pragma unroll
    for (int i = 0; i < 16; i++) {
        float a = 0.0f;
        #pragma unroll
        for (int j = 0; j < 16; j++) a += sM[i * 16 + j] * u[j];
        wn[i] = a + r * sv1[i] + sv2[i];
        gamma += u[i] * sv1[i];
        uv2   += u[i] * sv2[i];
    }
    float4* W4 = reinterpret_cast<float4*>(g_wn);
    #pragma unroll
    for (int i = 0; i < 4; i++)
        W4[n * 4 + i] = make_float4(wn[i * 4], wn[i * 4 + 1], wn[i * 4 + 2], wn[i * 4 + 3]);
    g_delta[n] = gamma + r * ssc[0] + ssc[1];
    g_eps[n]   = uv2 + r * ssc[1] + ssc[2];
}

// ---------------- 9) edge kernel: val = u_s . wn_d + r_s*delta_d + eps_d -----
__global__ void k_edge(const int* __restrict__ ei, float* __restrict__ out) {
    int e = blockIdx.x * blockDim.x + threadIdx.x;
    if (e >= EE) return;
    int s = ei[e];
    int d = ei[EE + e];
    const float4* U = reinterpret_cast<const float4*>(g_u);
    const float4* W = reinterpret_cast<const float4*>(g_wn);
    float dot = 0.0f;
    #pragma unroll
    for (int i = 0; i < 4; i++) {
        float4 a = U[s * 4 + i];
        float4 b = W[d * 4 + i];
        dot += a.x * b.x + a.y * b.y + a.z * b.z + a.w * b.w;
    }
    float val = dot + __ldg(&g_r[s]) * __ldg(&g_delta[d]) + __ldg(&g_eps[d]);
    out[e] = 1.0f / (1.0f + __expf(-val));
}

// ---------------- launch ------------------------------------------------------
extern "C" void kernel_launch(void* const* d_in, const int* in_sizes, int n_in,
                              void* d_out, int out_size) {
    const float* z  = (const float*)d_in[0];
    const int*   ei = (const int*)d_in[1];      // edge_index: int32 (JAX x64 off)
    const float* W1 = (const float*)d_in[2];
    const float* b1 = (const float*)d_in[3];
    const float* W2 = (const float*)d_in[4];
    const float* b2 = (const float*)d_in[5];
    float* out = (float*)d_out;

    k_zero<<<(NN + 255) / 256, 256>>>();
    k_hist<<<(EE + 255) / 256, 256>>>(ei);
    k_dinv_t0<<<(NN * 16 + 255) / 256, 256>>>(z);
    k_rowptr<<<(NN + 511) / 512, 512>>>();
    k_scatter<<<(EE + 255) / 256, 256>>>(ei);
    k_paramsA<<<1, 256>>>(W1, b1, W2);
    k_paramsB<<<1, 256>>>(b2);
    k_agg_p1<<<(NN * 32 + 255) / 256, 256>>>();
    k_agg_p2<<<(NN * 32 + 255) / 256, 256>>>();
    k_nodes<<<(NN + 255) / 256, 256>>>();
    k_edge<<<(EE + 255) / 256, 256>>>(ei, out);
}